// round 9
// baseline (speedup 1.0000x reference)
#include <cuda_runtime.h>

#define C   32
#define HF  96
#define WF  192
#define DD  192
#define HOUT 384
#define WOUT 768
#define ND  48
#define CHW (HF*WF)
#define COST_ELEMS (DD*HF*WF)
#define TP  (WF + 16)          // padded t/it rows: 16 zero floats before idx 0

// ---- packed f32x2 helpers (sm_103a) ----------------------------------------
__device__ __forceinline__ unsigned long long pack2(float lo, float hi) {
    unsigned long long r;
    asm("mov.b64 %0, {%1, %2};" : "=l"(r) : "f"(lo), "f"(hi));
    return r;
}
__device__ __forceinline__ void fma2(unsigned long long& acc,
                                     unsigned long long a, unsigned long long b) {
    asm("fma.rn.f32x2 %0, %1, %2, %0;" : "+l"(acc) : "l"(a), "l"(b));
}
__device__ __forceinline__ float2 unpack2(unsigned long long v) {
    float lo, hi;
    asm("mov.b64 {%0, %1}, %2;" : "=f"(lo), "=f"(hi) : "l"(v));
    return make_float2(lo, hi);
}

// ---------------------------------------------------------------------------
// Kernel 1: cosine cost volume, normalization deferred to store time.
// (unchanged from R8: measured ~8.7us)
// ---------------------------------------------------------------------------
__global__ __launch_bounds__(768, 1) void cost_kernel(
    const float* __restrict__ ref, const float* __restrict__ tgt,
    float* __restrict__ out)
{
    extern __shared__ float smbuf[];
    float (*r)[C][WF]  = reinterpret_cast<float (*)[C][WF]>(smbuf);
    float (*t)[C][TP]  = reinterpret_cast<float (*)[C][TP]>(smbuf + 2*C*WF);
    float* part_r      = smbuf + 2*C*WF + 2*C*TP;          // [384]
    float* part_t      = part_r + 2*WF;                    // [384]
    float (*ir)[WF]    = reinterpret_cast<float (*)[WF]>(part_t + 2*WF);
    float (*itp)[TP]   = reinterpret_cast<float (*)[TP]>(
                             reinterpret_cast<float*>(ir) + 2*WF);

    const int hp  = blockIdx.x;
    const int by  = blockIdx.y;
    const int tid = threadIdx.x;
    const int hrow0 = hp * 2;

    if (tid < 256) {
        int row = tid / 128;
        int c   = (tid / 4) % C;
        int q   = tid % 4;
        *reinterpret_cast<float4*>(&t[row][c][q*4]) = make_float4(0.f,0.f,0.f,0.f);
    } else if (tid < 264) {
        int idx = tid - 256;
        int row = idx / 4;
        int q   = idx % 4;
        *reinterpret_cast<float4*>(&itp[row][q*4]) = make_float4(0.f,0.f,0.f,0.f);
    }

    #pragma unroll
    for (int j = 0; j < 4; j++) {
        int k   = tid + j*768;
        int c   = k / 48;
        int kk  = k % 48;
        int row = c / C;
        int cc  = c % C;
        *reinterpret_cast<float4*>(&r[row][cc][kk*4]) =
            *reinterpret_cast<const float4*>(ref + cc*CHW + (hrow0+row)*WF + kk*4);
        *reinterpret_cast<float4*>(&t[row][cc][16 + kk*4]) =
            *reinterpret_cast<const float4*>(tgt + cc*CHW + (hrow0+row)*WF + kk*4);
    }
    __syncthreads();

    {
        int col  = tid % 384;
        int half = tid / 384;
        int row  = col / WF;
        int w    = col % WF;
        float sr = 0.f, st = 0.f;
        int cbase = half * 16;
        #pragma unroll
        for (int c = 0; c < 16; c++) {
            float a = r[row][cbase + c][w];      sr = fmaf(a, a, sr);
            float b = t[row][cbase + c][16 + w]; st = fmaf(b, b, st);
        }
        if (half) { part_r[col] = sr; part_t[col] = st; }
        __syncthreads();
        if (!half) {
            ir[row][w]       = rsqrtf(sr + part_r[col] + 1e-12f);
            itp[row][16 + w] = rsqrtf(st + part_t[col] + 1e-12f);
        }
    }
    __syncthreads();

    const int hr = (tid >= 384) ? 1 : 0;
    const int tm = tid - hr*384;
    const int wq = tm % 48;
    const int dq = tm / 48;
    const int w0 = wq * 4;
    const int d0 = 8 * (3*dq + by);
    const int h  = hrow0 + hr;

    unsigned long long axy0[8], azw0[8];
    #pragma unroll
    for (int i = 0; i < 8; i++) { axy0[i] = 0ULL; azw0[i] = 0ULL; }

    const int pb = 16 + w0 - d0 - 8;

    if (w0 - d0 >= 0) {
        for (int c = 0; c < C; c++) {
            float4 a  = *reinterpret_cast<const float4*>(&r[hr][c][w0]);
            float4 v0 = *reinterpret_cast<const float4*>(&t[hr][c][pb]);
            float4 v1 = *reinterpret_cast<const float4*>(&t[hr][c][pb + 4]);
            float4 v2 = *reinterpret_cast<const float4*>(&t[hr][c][pb + 8]);
            float e[12] = {v0.x, v0.y, v0.z, v0.w,
                           v1.x, v1.y, v1.z, v1.w,
                           v2.x, v2.y, v2.z, v2.w};
            unsigned long long pxy = pack2(a.x, a.y);
            unsigned long long pzw = pack2(a.z, a.w);
            #pragma unroll
            for (int j = 1; j <= 10; j++) {
                unsigned long long P = pack2(e[j], e[j+1]);
                if (j <= 8) fma2(axy0[8 - j], pxy, P);
                if (j >= 3) fma2(azw0[10 - j], pzw, P);
            }
        }
        float4 irq = *reinterpret_cast<const float4*>(&ir[hr][w0]);
        float4 s0 = *reinterpret_cast<const float4*>(&itp[hr][pb]);
        float4 s1 = *reinterpret_cast<const float4*>(&itp[hr][pb + 4]);
        float4 s2 = *reinterpret_cast<const float4*>(&itp[hr][pb + 8]);
        float e[12] = {s0.x, s0.y, s0.z, s0.w,
                       s1.x, s1.y, s1.z, s1.w,
                       s2.x, s2.y, s2.z, s2.w};
        #pragma unroll
        for (int i = 0; i < 8; i++) {
            float2 xy = unpack2(axy0[i]);
            float2 zw = unpack2(azw0[i]);
            float4 o;
            o.x = xy.x * irq.x * e[8  - i];
            o.y = xy.y * irq.y * e[9  - i];
            o.z = zw.x * irq.z * e[10 - i];
            o.w = zw.y * irq.w * e[11 - i];
            *reinterpret_cast<float4*>(&out[((d0 + i)*HF + h)*WF + w0]) = o;
        }
    } else {
        float4 z = make_float4(0.f, 0.f, 0.f, 0.f);
        #pragma unroll
        for (int i = 0; i < 8; i++)
            *reinterpret_cast<float4*>(&out[((d0 + i)*HF + h)*WF + w0]) = z;
    }
}

// ---------------------------------------------------------------------------
// Kernel 2: fused trilinear upsample + argmax + clamp(.,1).
// TWO pixels per thread: wo=2p and 2p+1 always share w0 (incl. clamped
// edges), so corner loads + h-lerp are shared; s_j = hA + fw_j*(hB-hA).
// x8-scaled candidate scan (exact, order-preserving):
// cand(e) = 7*s[e] + max(s[e-1],s[e+1]); exact samples 8*s[0] (k=0) and
// 8*s[47] (k=190). First-occurrence ties preserved (ascending e, strict >).
// Block 256 threads -> 64w x 8h pixels; grid (12, 48).
// ---------------------------------------------------------------------------
#define SSTR 52
#define NCOL 18

__device__ __forceinline__ void chunk8p(const float* __restrict__ c00,
                                        const float* __restrict__ c01,
                                        const float* __restrict__ c10,
                                        const float* __restrict__ c11,
                                        int dbase, float fh,
                                        float fw0, float fw1,
                                        float* __restrict__ s0,
                                        float* __restrict__ s1)
{
    #pragma unroll
    for (int half = 0; half < 2; half++) {
        float4 v00 = *reinterpret_cast<const float4*>(c00 + dbase + half*4);
        float4 v01 = *reinterpret_cast<const float4*>(c01 + dbase + half*4);
        float4 v10 = *reinterpret_cast<const float4*>(c10 + dbase + half*4);
        float4 v11 = *reinterpret_cast<const float4*>(c11 + dbase + half*4);
        float hA, hB, df;
        hA = fmaf(fh, v10.x - v00.x, v00.x);
        hB = fmaf(fh, v11.x - v01.x, v01.x);
        df = hB - hA;
        s0[half*4+0] = fmaf(fw0, df, hA);
        s1[half*4+0] = fmaf(fw1, df, hA);
        hA = fmaf(fh, v10.y - v00.y, v00.y);
        hB = fmaf(fh, v11.y - v01.y, v01.y);
        df = hB - hA;
        s0[half*4+1] = fmaf(fw0, df, hA);
        s1[half*4+1] = fmaf(fw1, df, hA);
        hA = fmaf(fh, v10.z - v00.z, v00.z);
        hB = fmaf(fh, v11.z - v01.z, v01.z);
        df = hB - hA;
        s0[half*4+2] = fmaf(fw0, df, hA);
        s1[half*4+2] = fmaf(fw1, df, hA);
        hA = fmaf(fh, v10.w - v00.w, v00.w);
        hB = fmaf(fh, v11.w - v01.w, v01.w);
        df = hB - hA;
        s0[half*4+3] = fmaf(fw0, df, hA);
        s1[half*4+3] = fmaf(fw1, df, hA);
    }
}

__device__ __forceinline__ float interp1(const float* __restrict__ c00,
                                         const float* __restrict__ c01,
                                         const float* __restrict__ c10,
                                         const float* __restrict__ c11,
                                         int d, float fh, float fw)
{
    float hA = fmaf(fh, c10[d] - c00[d], c00[d]);
    float hB = fmaf(fh, c11[d] - c01[d], c01[d]);
    return fmaf(fw, hB - hA, hA);
}

__device__ __forceinline__ void scan_head(const float* __restrict__ s,
                                          float& best, int& bestE)
{
    #pragma unroll
    for (int e = 0; e < 7; e++) {
        float nb = (e == 0) ? s[1] : fmaxf(s[e-1], s[e+1]);
        float cand = fmaf(7.0f, s[e], nb);
        if (cand > best) { best = cand; bestE = e; }
    }
}

__device__ __forceinline__ void scan_mid(const float* __restrict__ p,
                                         const float* __restrict__ c,
                                         int qb, float& best, int& bestE)
{
    {   float nb = fmaxf(p[6], c[0]);
        float cand = fmaf(7.0f, p[7], nb);
        if (cand > best) { best = cand; bestE = qb - 1; } }
    {   float nb = fmaxf(p[7], c[1]);
        float cand = fmaf(7.0f, c[0], nb);
        if (cand > best) { best = cand; bestE = qb; } }
    #pragma unroll
    for (int j = 1; j < 7; j++) {
        float nb = fmaxf(c[j-1], c[j+1]);
        float cand = fmaf(7.0f, c[j], nb);
        if (cand > best) { best = cand; bestE = qb + j; }
    }
}

__device__ __forceinline__ int decode_k(int bestE, float best, float s47x8,
                                        const float* c00, const float* c01,
                                        const float* c10, const float* c11,
                                        float fh, float fw)
{
    int k;
    if (s47x8 > best) {
        k = 4*(ND-1) + 2;                   // 190: exact sample s[47]
    } else if (bestE < 0) {
        k = 0;
    } else {
        float smL = -3.0e38f, smR = -3.0e38f;
        if (bestE > 0)      smL = interp1(c00, c01, c10, c11, bestE - 1, fh, fw);
        if (bestE < ND - 1) smR = interp1(c00, c01, c10, c11, bestE + 1, fh, fw);
        k = 4*bestE + 1 + ((smR > smL) ? 1 : 0);   // tie -> left (smaller k)
    }
    return max(k, 1);
}

__global__ __launch_bounds__(256) void pred_kernel(
    const float* __restrict__ cost, float* __restrict__ pred)
{
    __shared__ float sc[4][NCOL][SSTR];
    const int tx = threadIdx.x, ty = threadIdx.y;
    const int tid = ty*32 + tx;
    const int hb = 2*(int)blockIdx.y - 1;
    const int wb = 16*(int)blockIdx.x - 1;

    for (int i = tid; i < 4*NCOL*ND; i += 256) {
        int wc = i % NCOL;
        int hr = (i / NCOL) % 4;
        int d  = i / (4*NCOL);
        int hh = min(max(hb + hr, 0), HF - 1);
        int ww = min(max(wb + wc, 0), WF - 1);
        sc[hr][wc][d] = cost[(d*HF + hh)*WF + ww];
    }
    __syncthreads();

    const int wo0 = blockIdx.x*64 + 2*tx;   // even pixel of the pair
    const int ho  = blockIdx.y*8 + ty;

    float xh = fminf(fmaxf(0.25f*(float)ho - 0.375f, 0.f), (float)(HF - 1));
    int   h0 = min((int)xh, HF - 2);
    float fh = xh - (float)h0;

    float xw0 = fminf(fmaxf(0.25f*(float)wo0 - 0.375f, 0.f), (float)(WF - 1));
    float xw1 = fminf(fmaxf(0.25f*(float)(wo0+1) - 0.375f, 0.f), (float)(WF - 1));
    int   w0  = min((int)xw0, WF - 2);      // shared by both pixels
    float fw0 = xw0 - (float)w0;
    float fw1 = xw1 - (float)w0;

    const int lh = h0 - hb;
    const int lw = w0 - wb;
    const float* c00 = &sc[lh][lw][0];
    const float* c01 = &sc[lh][lw+1][0];
    const float* c10 = &sc[lh+1][lw][0];
    const float* c11 = &sc[lh+1][lw+1][0];

    float a0[8], a1[8], b0[8], b1[8];
    float best0, best1;
    int bestE0 = -1, bestE1 = -1;

    chunk8p(c00, c01, c10, c11, 0, fh, fw0, fw1, a0, a1);
    best0 = 8.0f * a0[0];
    best1 = 8.0f * a1[0];
    scan_head(a0, best0, bestE0);
    scan_head(a1, best1, bestE1);

    chunk8p(c00, c01, c10, c11,  8, fh, fw0, fw1, b0, b1);
    scan_mid(a0, b0,  8, best0, bestE0); scan_mid(a1, b1,  8, best1, bestE1);
    chunk8p(c00, c01, c10, c11, 16, fh, fw0, fw1, a0, a1);
    scan_mid(b0, a0, 16, best0, bestE0); scan_mid(b1, a1, 16, best1, bestE1);
    chunk8p(c00, c01, c10, c11, 24, fh, fw0, fw1, b0, b1);
    scan_mid(a0, b0, 24, best0, bestE0); scan_mid(a1, b1, 24, best1, bestE1);
    chunk8p(c00, c01, c10, c11, 32, fh, fw0, fw1, a0, a1);
    scan_mid(b0, a0, 32, best0, bestE0); scan_mid(b1, a1, 32, best1, bestE1);
    chunk8p(c00, c01, c10, c11, 40, fh, fw0, fw1, b0, b1);
    scan_mid(a0, b0, 40, best0, bestE0); scan_mid(a1, b1, 40, best1, bestE1);

    {   // e = 47
        float nb0 = b0[6], nb1 = b1[6];
        float cand0 = fmaf(7.0f, b0[7], nb0);
        float cand1 = fmaf(7.0f, b1[7], nb1);
        if (cand0 > best0) { best0 = cand0; bestE0 = 47; }
        if (cand1 > best1) { best1 = cand1; bestE1 = 47; }
    }

    int k0 = decode_k(bestE0, best0, 8.0f*b0[7], c00, c01, c10, c11, fh, fw0);
    int k1 = decode_k(bestE1, best1, 8.0f*b1[7], c00, c01, c10, c11, fh, fw1);

    *reinterpret_cast<float2*>(&pred[ho*WOUT + wo0]) =
        make_float2((float)k0, (float)k1);
}

// ---------------------------------------------------------------------------
extern "C" void kernel_launch(void* const* d_in, const int* in_sizes, int n_in,
                              void* d_out, int out_size)
{
    const float* left  = (const float*)d_in[0];
    const float* right = (const float*)d_in[1];
    float* out = (float*)d_out;

    const int smem_bytes =
        (2*C*WF + 2*C*TP + 2*WF + 2*WF + 2*WF + 2*TP) * (int)sizeof(float);
    cudaFuncSetAttribute(cost_kernel,
                         cudaFuncAttributeMaxDynamicSharedMemorySize, smem_bytes);

    dim3 g1(HF/2, 3), b1(768);
    cost_kernel<<<g1, b1, smem_bytes>>>(left, right, out);

    dim3 g2(WOUT/64, HOUT/8), b2(32, 8);
    pred_kernel<<<g2, b2>>>(out, out + COST_ELEMS);
}